// round 3
// baseline (speedup 1.0000x reference)
#include <cuda_runtime.h>
#include <math.h>

// Problem constants (fixed by the reference)
#define NN   50000
#define EE   800000
#define FIN  128
#define HH   4
#define HIDC 32
#define FF   128          // HH*HIDC
#define NEG_SLOPE 0.2f

// ---------------- scratch (device globals; no allocation allowed) ----------------
__device__ float g_feat[NN * FF];     // current layer's linear features
__device__ float g_h1  [NN * FF];     // layer-1 output (post relu)
__device__ float g_el  [NN * HH];
__device__ float g_er  [NN * HH];
__device__ float g_Wt  [FF * FF];     // transposed weight (reused per layer)
__device__ int   g_rowptr[NN + 1];
__device__ int   g_wp    [NN];
__device__ int   g_srcs  [EE];        // src node ids sorted by dst (CSR payload)

// ---------------- small helpers ----------------
__device__ __forceinline__ float lrelu(float v) { return v > 0.f ? v : NEG_SLOPE * v; }

// ---------------- CSR build ----------------
__global__ void k_zero_rowptr() {
    int i = blockIdx.x * blockDim.x + threadIdx.x;
    if (i <= NN) g_rowptr[i] = 0;
}

__global__ void k_hist(const int* __restrict__ dst) {
    int e = blockIdx.x * blockDim.x + threadIdx.x;
    if (e < EE) atomicAdd(&g_rowptr[dst[e] + 1], 1);
}

// single-block inclusive scan over rowptr[1..NN]
__global__ void k_scan() {
    __shared__ int sums[1024];
    const int T = 1024;
    int t = threadIdx.x;
    const int chunk = (NN + T - 1) / T;     // 49
    int start = 1 + t * chunk;
    int end = start + chunk; if (end > NN + 1) end = NN + 1;
    int run = 0;
    for (int i = start; i < end; i++) { run += g_rowptr[i]; g_rowptr[i] = run; }
    sums[t] = run;
    __syncthreads();
    // Hillis-Steele inclusive scan of per-thread totals
    for (int off = 1; off < T; off <<= 1) {
        int v = (t >= off) ? sums[t - off] : 0;
        __syncthreads();
        sums[t] += v;
        __syncthreads();
    }
    int add = (t > 0) ? sums[t - 1] : 0;
    for (int i = start; i < end; i++) g_rowptr[i] += add;
}

__global__ void k_copy_wp() {
    int i = blockIdx.x * blockDim.x + threadIdx.x;
    if (i < NN) g_wp[i] = g_rowptr[i];
}

__global__ void k_scatter(const int* __restrict__ src, const int* __restrict__ dst) {
    int e = blockIdx.x * blockDim.x + threadIdx.x;
    if (e < EE) {
        int pos = atomicAdd(&g_wp[dst[e]], 1);
        g_srcs[pos] = src[e];
    }
}

// ---------------- weight transpose (128x128) ----------------
__global__ void k_transpose(const float* __restrict__ W) {
    int i = blockIdx.x * blockDim.x + threadIdx.x;   // i = n*128 + k
    if (i < FF * FF) {
        int n = i >> 7, k = i & 127;
        g_Wt[i] = W[k * FF + n];
    }
}

// ---------------- GEMM: out[r][c] = dot(X[r][:], Wt[c][:]), K=128, Ncols=128 ----------------
// 128 threads/block, 8 rows/block; each thread owns one output column over 8 rows.
__global__ void __launch_bounds__(128) k_gemm(const float* __restrict__ X,
                                              float* __restrict__ out) {
    __shared__ float4 Xs[8][32];
    const int tid = threadIdx.x;
    const int row0 = blockIdx.x * 8;

    const float4* X4 = (const float4*)X;
    #pragma unroll
    for (int r2 = 0; r2 < 2; r2++) {
        int li  = tid + r2 * 128;        // 0..255
        int row = li >> 5;
        int k4  = li & 31;
        int gr  = row0 + row;
        Xs[row][k4] = (gr < NN) ? X4[gr * 32 + k4] : make_float4(0.f, 0.f, 0.f, 0.f);
    }
    __syncthreads();

    float acc[8] = {0.f, 0.f, 0.f, 0.f, 0.f, 0.f, 0.f, 0.f};
    const float4* wrow = ((const float4*)g_Wt) + tid * 32;

    #pragma unroll
    for (int k4 = 0; k4 < 32; k4++) {
        float4 w = wrow[k4];
        #pragma unroll
        for (int r = 0; r < 8; r++) {
            float4 xv = Xs[r][k4];
            acc[r] = fmaf(xv.x, w.x, acc[r]);
            acc[r] = fmaf(xv.y, w.y, acc[r]);
            acc[r] = fmaf(xv.z, w.z, acc[r]);
            acc[r] = fmaf(xv.w, w.w, acc[r]);
        }
    }
    #pragma unroll
    for (int r = 0; r < 8; r++) {
        int gr = row0 + r;
        if (gr < NN) out[gr * FF + tid] = acc[r];
    }
}

// ---------------- el/er: per-node, per-head dot(feat, al/ar) ----------------
// one warp per node; lane l holds channels 4l..4l+3 (head = l>>3)
__global__ void __launch_bounds__(256) k_elr(const float* __restrict__ feat,
                                             const float* __restrict__ al,
                                             const float* __restrict__ ar) {
    int n = blockIdx.x * 8 + (threadIdx.x >> 5);
    int lane = threadIdx.x & 31;
    if (n >= NN) return;
    float4 f  = ((const float4*)feat)[n * 32 + lane];
    float4 a4 = ((const float4*)al)[lane];
    float4 r4 = ((const float4*)ar)[lane];
    float sl = f.x * a4.x + f.y * a4.y + f.z * a4.z + f.w * a4.w;
    float sr = f.x * r4.x + f.y * r4.y + f.z * r4.z + f.w * r4.w;
    // reduce within 8-lane head group
    #pragma unroll
    for (int off = 4; off >= 1; off >>= 1) {
        sl += __shfl_xor_sync(0xffffffffu, sl, off);
        sr += __shfl_xor_sync(0xffffffffu, sr, off);
    }
    if ((lane & 7) == 0) {
        int h = lane >> 3;
        g_el[n * HH + h] = sl;
        g_er[n * HH + h] = sr;
    }
}

// ---------------- aggregation: one warp per dst node, 3-phase softmax ----------------
// MODE 0: out = relu(acc + bias)   -> writes [N,128]
// MODE 1: out[n] = 0.25 * sum_{h,j} (acc+b2)[h,j]*fcW[j] + fcb  -> writes [N]
template <int MODE>
__global__ void __launch_bounds__(256) k_agg(const float* __restrict__ feat,
                                             const float* __restrict__ bias,   // 128 floats
                                             const float* __restrict__ fcW,    // 32 floats (MODE 1)
                                             const float* __restrict__ fcb,    // 1 float  (MODE 1)
                                             float* __restrict__ out) {
    __shared__ float sh_a[8][32][4];
    __shared__ int   sh_s[8][32];

    const int w    = threadIdx.x >> 5;
    const int lane = threadIdx.x & 31;
    const int n    = blockIdx.x * 8 + w;
    if (n >= NN) return;

    const int p0  = g_rowptr[n];
    const int deg = g_rowptr[n + 1] - p0;
    const float4 er4 = ((const float4*)g_er)[n];
    const float4* elf = (const float4*)g_el;
    const float4* ff  = (const float4*)feat;

    // ---- phase 1: max ----
    float4 m = make_float4(-1e30f, -1e30f, -1e30f, -1e30f);
    for (int b = lane; b < deg; b += 32) {
        int s = g_srcs[p0 + b];
        float4 ev = elf[s];
        m.x = fmaxf(m.x, lrelu(ev.x + er4.x));
        m.y = fmaxf(m.y, lrelu(ev.y + er4.y));
        m.z = fmaxf(m.z, lrelu(ev.z + er4.z));
        m.w = fmaxf(m.w, lrelu(ev.w + er4.w));
    }
    #pragma unroll
    for (int off = 16; off >= 1; off >>= 1) {
        m.x = fmaxf(m.x, __shfl_xor_sync(0xffffffffu, m.x, off));
        m.y = fmaxf(m.y, __shfl_xor_sync(0xffffffffu, m.y, off));
        m.z = fmaxf(m.z, __shfl_xor_sync(0xffffffffu, m.z, off));
        m.w = fmaxf(m.w, __shfl_xor_sync(0xffffffffu, m.w, off));
    }

    // ---- phase 2: denom ----
    float4 den = make_float4(0.f, 0.f, 0.f, 0.f);
    for (int b = lane; b < deg; b += 32) {
        int s = g_srcs[p0 + b];
        float4 ev = elf[s];
        den.x += __expf(lrelu(ev.x + er4.x) - m.x);
        den.y += __expf(lrelu(ev.y + er4.y) - m.y);
        den.z += __expf(lrelu(ev.z + er4.z) - m.z);
        den.w += __expf(lrelu(ev.w + er4.w) - m.w);
    }
    #pragma unroll
    for (int off = 16; off >= 1; off >>= 1) {
        den.x += __shfl_xor_sync(0xffffffffu, den.x, off);
        den.y += __shfl_xor_sync(0xffffffffu, den.y, off);
        den.z += __shfl_xor_sync(0xffffffffu, den.z, off);
        den.w += __shfl_xor_sync(0xffffffffu, den.w, off);
    }
    float4 rd;
    rd.x = (deg > 0) ? 1.f / den.x : 0.f;
    rd.y = (deg > 0) ? 1.f / den.y : 0.f;
    rd.z = (deg > 0) ? 1.f / den.z : 0.f;
    rd.w = (deg > 0) ? 1.f / den.w : 0.f;

    // ---- phase 3: weighted gather-aggregate ----
    const int hl = lane >> 3;
    float4 acc = make_float4(0.f, 0.f, 0.f, 0.f);
    for (int base = 0; base < deg; base += 32) {
        int idx = base + lane;
        int s = 0;
        float4 a = make_float4(0.f, 0.f, 0.f, 0.f);
        if (idx < deg) {
            s = g_srcs[p0 + idx];
            float4 ev = elf[s];
            a.x = __expf(lrelu(ev.x + er4.x) - m.x) * rd.x;
            a.y = __expf(lrelu(ev.y + er4.y) - m.y) * rd.y;
            a.z = __expf(lrelu(ev.z + er4.z) - m.z) * rd.z;
            a.w = __expf(lrelu(ev.w + er4.w) - m.w) * rd.w;
        }
        sh_s[w][lane] = s;
        *((float4*)&sh_a[w][lane][0]) = a;
        __syncwarp();

        int cnt = deg - base; if (cnt > 32) cnt = 32;
        int i = 0;
        for (; i + 1 < cnt; i += 2) {
            int s0 = sh_s[w][i], s1 = sh_s[w][i + 1];
            float4 f0 = ff[s0 * 32 + lane];
            float4 f1 = ff[s1 * 32 + lane];
            float a0 = sh_a[w][i][hl];
            float a1 = sh_a[w][i + 1][hl];
            acc.x = fmaf(a0, f0.x, acc.x); acc.y = fmaf(a0, f0.y, acc.y);
            acc.z = fmaf(a0, f0.z, acc.z); acc.w = fmaf(a0, f0.w, acc.w);
            acc.x = fmaf(a1, f1.x, acc.x); acc.y = fmaf(a1, f1.y, acc.y);
            acc.z = fmaf(a1, f1.z, acc.z); acc.w = fmaf(a1, f1.w, acc.w);
        }
        if (i < cnt) {
            int s0 = sh_s[w][i];
            float4 f0 = ff[s0 * 32 + lane];
            float a0 = sh_a[w][i][hl];
            acc.x = fmaf(a0, f0.x, acc.x); acc.y = fmaf(a0, f0.y, acc.y);
            acc.z = fmaf(a0, f0.z, acc.z); acc.w = fmaf(a0, f0.w, acc.w);
        }
        __syncwarp();
    }

    // ---- epilogue ----
    float4 bv = ((const float4*)bias)[lane];
    if (MODE == 0) {
        float4 r;
        r.x = fmaxf(acc.x + bv.x, 0.f);
        r.y = fmaxf(acc.y + bv.y, 0.f);
        r.z = fmaxf(acc.z + bv.z, 0.f);
        r.w = fmaxf(acc.w + bv.w, 0.f);
        ((float4*)out)[n * 32 + lane] = r;
    } else {
        float4 fw = ((const float4*)fcW)[lane & 7];
        float p = (acc.x + bv.x) * fw.x + (acc.y + bv.y) * fw.y
                + (acc.z + bv.z) * fw.z + (acc.w + bv.w) * fw.w;
        #pragma unroll
        for (int off = 16; off >= 1; off >>= 1)
            p += __shfl_xor_sync(0xffffffffu, p, off);
        if (lane == 0) out[n] = p * 0.25f + fcb[0];
    }
}

// ---------------- launch ----------------
extern "C" void kernel_launch(void* const* d_in, const int* in_sizes, int n_in,
                              void* d_out, int out_size) {
    const float* x   = (const float*)d_in[0];
    const int*   src = (const int*)  d_in[1];
    const int*   dst = (const int*)  d_in[2];
    const float* W1  = (const float*)d_in[3];
    const float* al1 = (const float*)d_in[4];
    const float* ar1 = (const float*)d_in[5];
    const float* b1  = (const float*)d_in[6];
    const float* W2  = (const float*)d_in[7];
    const float* al2 = (const float*)d_in[8];
    const float* ar2 = (const float*)d_in[9];
    const float* b2  = (const float*)d_in[10];
    const float* fcW = (const float*)d_in[11];
    const float* fcb = (const float*)d_in[12];
    float* out = (float*)d_out;

    float* feat = nullptr; float* h1 = nullptr;
    cudaGetSymbolAddress((void**)&feat, g_feat);
    cudaGetSymbolAddress((void**)&h1,   g_h1);
    float* Wt = nullptr;
    cudaGetSymbolAddress((void**)&Wt, g_Wt);

    const int TB = 256;
    const int nodeBlocks = (NN + 7) / 8;     // 6250

    // CSR build (reused by both layers)
    k_zero_rowptr<<<(NN + 1 + TB - 1) / TB, TB>>>();
    k_hist<<<(EE + TB - 1) / TB, TB>>>(dst);
    k_scan<<<1, 1024>>>();
    k_copy_wp<<<(NN + TB - 1) / TB, TB>>>();
    k_scatter<<<(EE + TB - 1) / TB, TB>>>(src, dst);

    // ---- layer 1 ----
    k_transpose<<<(FF * FF + TB - 1) / TB, TB>>>(W1);
    k_gemm<<<nodeBlocks, 128>>>(x, feat);
    k_elr<<<nodeBlocks, 256>>>(feat, al1, ar1);
    k_agg<0><<<nodeBlocks, 256>>>(feat, b1, nullptr, nullptr, h1);

    // ---- layer 2 + fc ----
    k_transpose<<<(FF * FF + TB - 1) / TB, TB>>>(W2);
    k_gemm<<<nodeBlocks, 128>>>(h1, feat);
    k_elr<<<nodeBlocks, 256>>>(feat, al2, ar2);
    k_agg<1><<<nodeBlocks, 256>>>(feat, b2, fcW, fcb, out);
}

// round 4
// speedup vs baseline: 1.3113x; 1.3113x over previous
#include <cuda_runtime.h>
#include <math.h>

// Problem constants (fixed by the reference)
#define NN   50000
#define EE   800000
#define FIN  128
#define HH   4
#define HIDC 32
#define FF   128          // HH*HIDC
#define NEG_SLOPE 0.2f

// ---------------- scratch (device globals; no allocation allowed) ----------------
__device__ float g_feat[NN * FF];     // current layer's linear features
__device__ float g_h1  [NN * FF];     // layer-1 output (post relu)
__device__ float g_el  [NN * HH];
__device__ float g_er  [NN * HH];
__device__ float g_Wt  [FF * FF];     // transposed weight (reused per layer)
__device__ int   g_rowptr[NN + 1];
__device__ int   g_wp    [NN];
__device__ int   g_srcs  [EE];        // src node ids sorted by dst (CSR payload)

// ---------------- small helpers ----------------
__device__ __forceinline__ float lrelu(float v) { return v > 0.f ? v : NEG_SLOPE * v; }

// packed dual-FP32 FMA (Blackwell f32x2 pipe: 2 MACs per issue slot)
__device__ __forceinline__ void ffma2(unsigned long long& d,
                                      unsigned long long a,
                                      unsigned long long b) {
    asm("fma.rn.f32x2 %0, %1, %2, %0;" : "+l"(d) : "l"(a), "l"(b));
}

// ---------------- CSR build ----------------
__global__ void k_zero_rowptr() {
    int i = blockIdx.x * blockDim.x + threadIdx.x;
    if (i <= NN) g_rowptr[i] = 0;
}

__global__ void k_hist(const int* __restrict__ dst) {
    int e = blockIdx.x * blockDim.x + threadIdx.x;
    if (e < EE) atomicAdd(&g_rowptr[dst[e] + 1], 1);
}

// single-block inclusive scan over rowptr[1..NN]
__global__ void k_scan() {
    __shared__ int sums[1024];
    const int T = 1024;
    int t = threadIdx.x;
    const int chunk = (NN + T - 1) / T;     // 49
    int start = 1 + t * chunk;
    int end = start + chunk; if (end > NN + 1) end = NN + 1;
    int run = 0;
    for (int i = start; i < end; i++) { run += g_rowptr[i]; g_rowptr[i] = run; }
    sums[t] = run;
    __syncthreads();
    for (int off = 1; off < T; off <<= 1) {
        int v = (t >= off) ? sums[t - off] : 0;
        __syncthreads();
        sums[t] += v;
        __syncthreads();
    }
    int add = (t > 0) ? sums[t - 1] : 0;
    for (int i = start; i < end; i++) g_rowptr[i] += add;
}

__global__ void k_copy_wp() {
    int i = blockIdx.x * blockDim.x + threadIdx.x;
    if (i < NN) g_wp[i] = g_rowptr[i];
}

__global__ void k_scatter(const int* __restrict__ src, const int* __restrict__ dst) {
    int e = blockIdx.x * blockDim.x + threadIdx.x;
    if (e < EE) {
        int pos = atomicAdd(&g_wp[dst[e]], 1);
        g_srcs[pos] = src[e];
    }
}

// ---------------- weight transpose (128x128) ----------------
__global__ void k_transpose(const float* __restrict__ W) {
    int i = blockIdx.x * blockDim.x + threadIdx.x;   // i = n*128 + k
    if (i < FF * FF) {
        int n = i >> 7, k = i & 127;
        g_Wt[i] = W[k * FF + n];
    }
}

// ---------------- GEMM: out[r][c] = dot(X[r][:], Wt[c][:]), K=128, Ncols=128 ----------------
// 128 threads/block, 16 rows/block; each thread owns one output column over 16 rows.
// Inner product done with packed fma.rn.f32x2 (2 MACs / issue slot).
__global__ void __launch_bounds__(128) k_gemm(const float* __restrict__ X,
                                              float* __restrict__ out) {
    __shared__ float4 Xs[16][32];
    const int tid = threadIdx.x;
    const int row0 = blockIdx.x * 16;

    const float4* X4 = (const float4*)X;
    #pragma unroll
    for (int i = 0; i < 4; i++) {
        int li  = tid + i * 128;         // 0..511
        int row = li >> 5;
        int k4  = li & 31;
        int gr  = row0 + row;
        Xs[row][k4] = (gr < NN) ? X4[gr * 32 + k4] : make_float4(0.f, 0.f, 0.f, 0.f);
    }
    __syncthreads();

    unsigned long long acc[16];
    #pragma unroll
    for (int r = 0; r < 16; r++) acc[r] = 0ull;

    const float4* wrow = ((const float4*)g_Wt) + tid * 32;

    union F4U { float4 f; unsigned long long u[2]; };

    #pragma unroll 4
    for (int k4 = 0; k4 < 32; k4++) {
        F4U w; w.f = wrow[k4];
        #pragma unroll
        for (int r = 0; r < 16; r++) {
            F4U xv; xv.f = Xs[r][k4];
            ffma2(acc[r], xv.u[0], w.u[0]);
            ffma2(acc[r], xv.u[1], w.u[1]);
        }
    }
    #pragma unroll
    for (int r = 0; r < 16; r++) {
        int gr = row0 + r;
        if (gr < NN) {
            float2 p = *(float2*)&acc[r];
            out[gr * FF + tid] = p.x + p.y;
        }
    }
}

// ---------------- el/er: per-node, per-head dot(feat, al/ar) ----------------
__global__ void __launch_bounds__(256) k_elr(const float* __restrict__ feat,
                                             const float* __restrict__ al,
                                             const float* __restrict__ ar) {
    int n = blockIdx.x * 8 + (threadIdx.x >> 5);
    int lane = threadIdx.x & 31;
    if (n >= NN) return;
    float4 f  = ((const float4*)feat)[n * 32 + lane];
    float4 a4 = ((const float4*)al)[lane];
    float4 r4 = ((const float4*)ar)[lane];
    float sl = f.x * a4.x + f.y * a4.y + f.z * a4.z + f.w * a4.w;
    float sr = f.x * r4.x + f.y * r4.y + f.z * r4.z + f.w * r4.w;
    #pragma unroll
    for (int off = 4; off >= 1; off >>= 1) {
        sl += __shfl_xor_sync(0xffffffffu, sl, off);
        sr += __shfl_xor_sync(0xffffffffu, sr, off);
    }
    if ((lane & 7) == 0) {
        int h = lane >> 3;
        g_el[n * HH + h] = sl;
        g_er[n * HH + h] = sr;
    }
}

// ---------------- aggregation: one warp per dst node, SINGLE fused pass ----------------
// out = (sum_i ex_i * feat_i) / (sum_i ex_i)  with ex = exp(lrelu(el+er)) (no max shift:
// |e| is O(8) here, far from fp32 exp overflow, and the normalized ratio is identical).
// MODE 0: out = relu(acc + bias)   -> writes [N,128]
// MODE 1: out[n] = 0.25 * sum_{h,j} (acc+b2)[h,j]*fcW[j] + fcb  -> writes [N]
template <int MODE>
__global__ void __launch_bounds__(256) k_agg(const float* __restrict__ feat,
                                             const float* __restrict__ bias,   // 128 floats
                                             const float* __restrict__ fcW,    // 32 floats (MODE 1)
                                             const float* __restrict__ fcb,    // 1 float  (MODE 1)
                                             float* __restrict__ out) {
    __shared__ float sh_a[8][32][4];
    __shared__ int   sh_s[8][32];

    const int w    = threadIdx.x >> 5;
    const int lane = threadIdx.x & 31;
    const int n    = blockIdx.x * 8 + w;
    if (n >= NN) return;

    const int p0  = g_rowptr[n];
    const int deg = g_rowptr[n + 1] - p0;
    const float4 er4 = ((const float4*)g_er)[n];
    const float4* elf = (const float4*)g_el;
    const float4* ff  = (const float4*)feat;

    const int hl = lane >> 3;
    float4 acc = make_float4(0.f, 0.f, 0.f, 0.f);
    float4 den = make_float4(0.f, 0.f, 0.f, 0.f);

    for (int base = 0; base < deg; base += 32) {
        int idx = base + lane;
        int s = 0;
        float4 a = make_float4(0.f, 0.f, 0.f, 0.f);
        if (idx < deg) {
            s = g_srcs[p0 + idx];
            float4 ev = elf[s];
            a.x = __expf(lrelu(ev.x + er4.x));
            a.y = __expf(lrelu(ev.y + er4.y));
            a.z = __expf(lrelu(ev.z + er4.z));
            a.w = __expf(lrelu(ev.w + er4.w));
            den.x += a.x; den.y += a.y; den.z += a.z; den.w += a.w;
        }
        sh_s[w][lane] = s;
        *((float4*)&sh_a[w][lane][0]) = a;
        __syncwarp();

        int cnt = deg - base; if (cnt > 32) cnt = 32;
        int i = 0;
        for (; i + 1 < cnt; i += 2) {
            int s0 = sh_s[w][i], s1 = sh_s[w][i + 1];
            float4 f0 = ff[s0 * 32 + lane];
            float4 f1 = ff[s1 * 32 + lane];
            float a0 = sh_a[w][i][hl];
            float a1 = sh_a[w][i + 1][hl];
            acc.x = fmaf(a0, f0.x, acc.x); acc.y = fmaf(a0, f0.y, acc.y);
            acc.z = fmaf(a0, f0.z, acc.z); acc.w = fmaf(a0, f0.w, acc.w);
            acc.x = fmaf(a1, f1.x, acc.x); acc.y = fmaf(a1, f1.y, acc.y);
            acc.z = fmaf(a1, f1.z, acc.z); acc.w = fmaf(a1, f1.w, acc.w);
        }
        if (i < cnt) {
            int s0 = sh_s[w][i];
            float4 f0 = ff[s0 * 32 + lane];
            float a0 = sh_a[w][i][hl];
            acc.x = fmaf(a0, f0.x, acc.x); acc.y = fmaf(a0, f0.y, acc.y);
            acc.z = fmaf(a0, f0.z, acc.z); acc.w = fmaf(a0, f0.w, acc.w);
        }
        __syncwarp();
    }

    // reduce denominator across lanes (per head component)
    #pragma unroll
    for (int off = 16; off >= 1; off >>= 1) {
        den.x += __shfl_xor_sync(0xffffffffu, den.x, off);
        den.y += __shfl_xor_sync(0xffffffffu, den.y, off);
        den.z += __shfl_xor_sync(0xffffffffu, den.z, off);
        den.w += __shfl_xor_sync(0xffffffffu, den.w, off);
    }
    // this lane's 4 channels all belong to head hl
    float dh = (hl == 0) ? den.x : (hl == 1) ? den.y : (hl == 2) ? den.z : den.w;
    float rdh = (deg > 0) ? 1.f / dh : 0.f;
    acc.x *= rdh; acc.y *= rdh; acc.z *= rdh; acc.w *= rdh;

    // ---- epilogue ----
    float4 bv = ((const float4*)bias)[lane];
    if (MODE == 0) {
        float4 r;
        r.x = fmaxf(acc.x + bv.x, 0.f);
        r.y = fmaxf(acc.y + bv.y, 0.f);
        r.z = fmaxf(acc.z + bv.z, 0.f);
        r.w = fmaxf(acc.w + bv.w, 0.f);
        ((float4*)out)[n * 32 + lane] = r;
    } else {
        float4 fw = ((const float4*)fcW)[lane & 7];
        float p = (acc.x + bv.x) * fw.x + (acc.y + bv.y) * fw.y
                + (acc.z + bv.z) * fw.z + (acc.w + bv.w) * fw.w;
        #pragma unroll
        for (int off = 16; off >= 1; off >>= 1)
            p += __shfl_xor_sync(0xffffffffu, p, off);
        if (lane == 0) out[n] = p * 0.25f + fcb[0];
    }
}

// ---------------- launch ----------------
extern "C" void kernel_launch(void* const* d_in, const int* in_sizes, int n_in,
                              void* d_out, int out_size) {
    const float* x   = (const float*)d_in[0];
    const int*   src = (const int*)  d_in[1];
    const int*   dst = (const int*)  d_in[2];
    const float* W1  = (const float*)d_in[3];
    const float* al1 = (const float*)d_in[4];
    const float* ar1 = (const float*)d_in[5];
    const float* b1  = (const float*)d_in[6];
    const float* W2  = (const float*)d_in[7];
    const float* al2 = (const float*)d_in[8];
    const float* ar2 = (const float*)d_in[9];
    const float* b2  = (const float*)d_in[10];
    const float* fcW = (const float*)d_in[11];
    const float* fcb = (const float*)d_in[12];
    float* out = (float*)d_out;

    float* feat = nullptr; float* h1 = nullptr;
    cudaGetSymbolAddress((void**)&feat, g_feat);
    cudaGetSymbolAddress((void**)&h1,   g_h1);

    const int TB = 256;
    const int nodeBlocks8  = (NN + 7) / 8;      // 6250
    const int nodeBlocks16 = (NN + 15) / 16;    // 3125

    // CSR build (reused by both layers)
    k_zero_rowptr<<<(NN + 1 + TB - 1) / TB, TB>>>();
    k_hist<<<(EE + TB - 1) / TB, TB>>>(dst);
    k_scan<<<1, 1024>>>();
    k_copy_wp<<<(NN + TB - 1) / TB, TB>>>();
    k_scatter<<<(EE + TB - 1) / TB, TB>>>(src, dst);

    // ---- layer 1 ----
    k_transpose<<<(FF * FF + TB - 1) / TB, TB>>>(W1);
    k_gemm<<<nodeBlocks16, 128>>>(x, feat);
    k_elr<<<nodeBlocks8, 256>>>(feat, al1, ar1);
    k_agg<0><<<nodeBlocks8, 256>>>(feat, b1, nullptr, nullptr, h1);

    // ---- layer 2 + fc ----
    k_transpose<<<(FF * FF + TB - 1) / TB, TB>>>(W2);
    k_gemm<<<nodeBlocks16, 128>>>(h1, feat);
    k_elr<<<nodeBlocks8, 256>>>(feat, al2, ar2);
    k_agg<1><<<nodeBlocks8, 256>>>(feat, b2, fcW, fcb, out);
}

// round 5
// speedup vs baseline: 1.3353x; 1.0183x over previous
#include <cuda_runtime.h>
#include <math.h>

// Problem constants (fixed by the reference)
#define NN   50000
#define EE   800000
#define HH   4
#define FF   128          // HH*HID
#define NEG_SLOPE 0.2f

typedef unsigned long long ull;

// ---------------- scratch (device globals; no allocation allowed) ----------------
__device__ float g_feat[NN * FF];
__device__ float g_h1  [NN * FF];
__device__ float g_el  [NN * HH];
__device__ float g_er  [NN * HH];
__device__ float g_Wt1 [FF * FF];
__device__ float g_Wt2 [FF * FF];
__device__ int   g_rowptr[NN + 1];
__device__ int   g_wp    [NN];
__device__ int   g_srcs  [EE];

// ---------------- helpers ----------------
__device__ __forceinline__ float lrelu(float v) { return v > 0.f ? v : NEG_SLOPE * v; }
__device__ __forceinline__ void ffma2(ull& d, ull a, ull b) {
    asm("fma.rn.f32x2 %0, %1, %2, %0;" : "+l"(d) : "l"(a), "l"(b));
}
__device__ __forceinline__ ull addf2(ull a, ull b) {
    ull r; asm("add.rn.f32x2 %0, %1, %2;" : "=l"(r) : "l"(a), "l"(b)); return r;
}
__device__ __forceinline__ ull dup2(float a) {
    ull r; asm("mov.b64 %0, {%1, %1};" : "=l"(r) : "f"(a)); return r;
}
__device__ __forceinline__ ull pack2(float lo, float hi) {
    ull r; asm("mov.b64 %0, {%1, %2};" : "=l"(r) : "f"(lo), "f"(hi)); return r;
}
__device__ __forceinline__ float2 unpack2(ull v) {
    float2 p; asm("mov.b64 {%0, %1}, %2;" : "=f"(p.x), "=f"(p.y) : "l"(v)); return p;
}

// ---------------- prep: zero rowptr + transpose both weights ----------------
__global__ void k_prep(const float* __restrict__ W1, const float* __restrict__ W2) {
    int i = blockIdx.x * blockDim.x + threadIdx.x;
    if (i <= NN) g_rowptr[i] = 0;
    if (i < FF * FF) {
        int n = i >> 7, k = i & 127;
        g_Wt1[i] = W1[k * FF + n];
        g_Wt2[i] = W2[k * FF + n];
    }
}

__global__ void k_hist(const int* __restrict__ dst) {
    int e = blockIdx.x * blockDim.x + threadIdx.x;
    if (e < EE) atomicAdd(&g_rowptr[dst[e] + 1], 1);
}

// single-block inclusive scan over rowptr[1..NN]; also fills g_wp
__global__ void k_scan() {
    __shared__ int sums[1024];
    const int T = 1024;
    int t = threadIdx.x;
    const int chunk = (NN + T - 1) / T;
    int start = 1 + t * chunk;
    int end = start + chunk; if (end > NN + 1) end = NN + 1;
    int run = 0;
    for (int i = start; i < end; i++) { run += g_rowptr[i]; g_rowptr[i] = run; }
    sums[t] = run;
    __syncthreads();
    for (int off = 1; off < T; off <<= 1) {
        int v = (t >= off) ? sums[t - off] : 0;
        __syncthreads();
        sums[t] += v;
        __syncthreads();
    }
    int add = (t > 0) ? sums[t - 1] : 0;
    for (int i = start; i < end; i++) {
        int v = g_rowptr[i] + add;
        g_rowptr[i] = v;
        if (i < NN) g_wp[i] = v;
    }
    if (t == 0) g_wp[0] = 0;
}

__global__ void k_scatter(const int* __restrict__ src, const int* __restrict__ dst) {
    int e = blockIdx.x * blockDim.x + threadIdx.x;
    if (e < EE) {
        int pos = atomicAdd(&g_wp[dst[e]], 1);
        g_srcs[pos] = src[e];
    }
}

// ---------------- GEMM + fused el/er ----------------
// 64 threads/block, 16 rows/block, 2 columns/thread (c0=tid, c1=tid+64).
// Warp w covers columns [32w,32w+32) = head w, and [64+32w, 96+32w) = head w+2,
// so the el/er head reductions are exact warp reductions.
__global__ void __launch_bounds__(64) k_gemm(const float* __restrict__ X,
                                             const float* __restrict__ Wt,
                                             const float* __restrict__ al,
                                             const float* __restrict__ ar,
                                             float* __restrict__ out) {
    __shared__ float4 Xs[16][32];
    const int tid = threadIdx.x;
    const int row0 = blockIdx.x * 16;   // NN = 3125*16 exactly

    const float4* X4 = (const float4*)X;
    #pragma unroll
    for (int i = 0; i < 8; i++) {
        int li = tid + i * 64;
        int r = li >> 5, k4 = li & 31;
        Xs[r][k4] = X4[(row0 + r) * 32 + k4];
    }
    __syncthreads();

    const int c0 = tid, c1 = tid + 64;
    ull acc0[16], acc1[16];
    #pragma unroll
    for (int r = 0; r < 16; r++) { acc0[r] = 0ull; acc1[r] = 0ull; }

    const float4* w0 = ((const float4*)Wt) + c0 * 32;
    const float4* w1 = ((const float4*)Wt) + c1 * 32;

    union F4U { float4 f; ull u[2]; };

    #pragma unroll 4
    for (int k4 = 0; k4 < 32; k4++) {
        F4U wa; wa.f = w0[k4];
        F4U wb; wb.f = w1[k4];
        #pragma unroll
        for (int r = 0; r < 16; r++) {
            F4U xv; xv.f = Xs[r][k4];
            ffma2(acc0[r], xv.u[0], wa.u[0]);
            ffma2(acc0[r], xv.u[1], wa.u[1]);
            ffma2(acc1[r], xv.u[0], wb.u[0]);
            ffma2(acc1[r], xv.u[1], wb.u[1]);
        }
    }

    const float al0 = al[c0], ar0 = ar[c0];
    const float al1 = al[c1], ar1 = ar[c1];
    const int w = tid >> 5;

    #pragma unroll
    for (int r = 0; r < 16; r++) {
        float2 p0 = unpack2(acc0[r]); float f0 = p0.x + p0.y;
        float2 p1 = unpack2(acc1[r]); float f1 = p1.x + p1.y;
        int gr = row0 + r;
        out[gr * FF + c0] = f0;
        out[gr * FF + c1] = f1;
        ull q0 = pack2(f0 * al0, f0 * ar0);
        ull q1 = pack2(f1 * al1, f1 * ar1);
        #pragma unroll
        for (int off = 16; off >= 1; off >>= 1) {
            q0 = addf2(q0, __shfl_xor_sync(0xffffffffu, q0, off));
            q1 = addf2(q1, __shfl_xor_sync(0xffffffffu, q1, off));
        }
        if ((tid & 31) == 0) {
            float2 e0 = unpack2(q0), e1 = unpack2(q1);
            g_el[gr * HH + w]     = e0.x;  g_er[gr * HH + w]     = e0.y;
            g_el[gr * HH + w + 2] = e1.x;  g_er[gr * HH + w + 2] = e1.y;
        }
    }
}

// ---------------- aggregation: one warp per dst node, single fused pass ----------------
// out = (sum_i ex_i * feat_i) / (sum_i ex_i), ex = exp(lrelu(el+er)) (no max shift;
// |e| is O(8), far from fp32 exp overflow; normalized ratio identical).
template <int MODE>
__global__ void __launch_bounds__(256) k_agg(const float* __restrict__ feat,
                                             const float* __restrict__ bias,
                                             const float* __restrict__ fcW,
                                             const float* __restrict__ fcb,
                                             float* __restrict__ out) {
    __shared__ float sh_a[8][32][4];
    __shared__ int   sh_s[8][32];

    const int w    = threadIdx.x >> 5;
    const int lane = threadIdx.x & 31;
    const int n    = blockIdx.x * 8 + w;
    if (n >= NN) return;

    const int p0  = g_rowptr[n];
    const int deg = g_rowptr[n + 1] - p0;
    const float4 er4 = ((const float4*)g_er)[n];
    const float4* elf = (const float4*)g_el;
    const float4* ff  = (const float4*)feat;

    const int hl = lane >> 3;
    ull accA = 0ull, accB = 0ull;           // channels (x,y) and (z,w)
    float4 den = make_float4(0.f, 0.f, 0.f, 0.f);

    union F4U { float4 f; ull u[2]; };

    for (int base = 0; base < deg; base += 32) {
        int idx = base + lane;
        int s = 0;
        float4 a = make_float4(0.f, 0.f, 0.f, 0.f);
        if (idx < deg) {
            s = g_srcs[p0 + idx];
            float4 ev = elf[s];
            a.x = __expf(lrelu(ev.x + er4.x));
            a.y = __expf(lrelu(ev.y + er4.y));
            a.z = __expf(lrelu(ev.z + er4.z));
            a.w = __expf(lrelu(ev.w + er4.w));
            den.x += a.x; den.y += a.y; den.z += a.z; den.w += a.w;
        }
        sh_s[w][lane] = s;
        *((float4*)&sh_a[w][lane][0]) = a;
        __syncwarp();

        int cnt = deg - base; if (cnt > 32) cnt = 32;
        int i = 0;
        for (; i + 4 <= cnt; i += 4) {
            int s0 = sh_s[w][i],     s1 = sh_s[w][i + 1];
            int s2 = sh_s[w][i + 2], s3 = sh_s[w][i + 3];
            F4U f0, f1, f2, f3;
            f0.f = ff[s0 * 32 + lane];
            f1.f = ff[s1 * 32 + lane];
            f2.f = ff[s2 * 32 + lane];
            f3.f = ff[s3 * 32 + lane];
            ull d0 = dup2(sh_a[w][i][hl]);
            ull d1 = dup2(sh_a[w][i + 1][hl]);
            ull d2 = dup2(sh_a[w][i + 2][hl]);
            ull d3 = dup2(sh_a[w][i + 3][hl]);
            ffma2(accA, f0.u[0], d0); ffma2(accB, f0.u[1], d0);
            ffma2(accA, f1.u[0], d1); ffma2(accB, f1.u[1], d1);
            ffma2(accA, f2.u[0], d2); ffma2(accB, f2.u[1], d2);
            ffma2(accA, f3.u[0], d3); ffma2(accB, f3.u[1], d3);
        }
        for (; i < cnt; i++) {
            int s0 = sh_s[w][i];
            F4U f0; f0.f = ff[s0 * 32 + lane];
            ull d0 = dup2(sh_a[w][i][hl]);
            ffma2(accA, f0.u[0], d0); ffma2(accB, f0.u[1], d0);
        }
        __syncwarp();
    }

    // reduce denominator across lanes (per head component)
    #pragma unroll
    for (int off = 16; off >= 1; off >>= 1) {
        den.x += __shfl_xor_sync(0xffffffffu, den.x, off);
        den.y += __shfl_xor_sync(0xffffffffu, den.y, off);
        den.z += __shfl_xor_sync(0xffffffffu, den.z, off);
        den.w += __shfl_xor_sync(0xffffffffu, den.w, off);
    }
    float dh = (hl == 0) ? den.x : (hl == 1) ? den.y : (hl == 2) ? den.z : den.w;
    float rdh = (deg > 0) ? 1.f / dh : 0.f;

    float2 pA = unpack2(accA), pB = unpack2(accB);
    float4 acc = make_float4(pA.x * rdh, pA.y * rdh, pB.x * rdh, pB.y * rdh);

    float4 bv = ((const float4*)bias)[lane];
    if (MODE == 0) {
        float4 r;
        r.x = fmaxf(acc.x + bv.x, 0.f);
        r.y = fmaxf(acc.y + bv.y, 0.f);
        r.z = fmaxf(acc.z + bv.z, 0.f);
        r.w = fmaxf(acc.w + bv.w, 0.f);
        ((float4*)out)[n * 32 + lane] = r;
    } else {
        float4 fw = ((const float4*)fcW)[lane & 7];
        float p = (acc.x + bv.x) * fw.x + (acc.y + bv.y) * fw.y
                + (acc.z + bv.z) * fw.z + (acc.w + bv.w) * fw.w;
        #pragma unroll
        for (int off = 16; off >= 1; off >>= 1)
            p += __shfl_xor_sync(0xffffffffu, p, off);
        if (lane == 0) out[n] = p * 0.25f + fcb[0];
    }
}

// ---------------- launch ----------------
extern "C" void kernel_launch(void* const* d_in, const int* in_sizes, int n_in,
                              void* d_out, int out_size) {
    const float* x   = (const float*)d_in[0];
    const int*   src = (const int*)  d_in[1];
    const int*   dst = (const int*)  d_in[2];
    const float* W1  = (const float*)d_in[3];
    const float* al1 = (const float*)d_in[4];
    const float* ar1 = (const float*)d_in[5];
    const float* b1  = (const float*)d_in[6];
    const float* W2  = (const float*)d_in[7];
    const float* al2 = (const float*)d_in[8];
    const float* ar2 = (const float*)d_in[9];
    const float* b2  = (const float*)d_in[10];
    const float* fcW = (const float*)d_in[11];
    const float* fcb = (const float*)d_in[12];
    float* out = (float*)d_out;

    float *feat = nullptr, *h1 = nullptr, *Wt1 = nullptr, *Wt2 = nullptr;
    cudaGetSymbolAddress((void**)&feat, g_feat);
    cudaGetSymbolAddress((void**)&h1,   g_h1);
    cudaGetSymbolAddress((void**)&Wt1,  g_Wt1);
    cudaGetSymbolAddress((void**)&Wt2,  g_Wt2);

    const int TB = 256;
    const int nodeBlocks8  = (NN + 7) / 8;      // 6250
    const int gemmBlocks   = NN / 16;           // 3125

    // CSR build + weight prep
    k_prep<<<(NN + 1 + TB - 1) / TB, TB>>>(W1, W2);
    k_hist<<<(EE + TB - 1) / TB, TB>>>(dst);
    k_scan<<<1, 1024>>>();
    k_scatter<<<(EE + TB - 1) / TB, TB>>>(src, dst);

    // ---- layer 1 ----
    k_gemm<<<gemmBlocks, 64>>>(x, Wt1, al1, ar1, feat);
    k_agg<0><<<nodeBlocks8, 256>>>(feat, b1, nullptr, nullptr, h1);

    // ---- layer 2 + fc ----
    k_gemm<<<gemmBlocks, 64>>>(h1, Wt2, al2, ar2, feat);
    k_agg<1><<<nodeBlocks8, 256>>>(feat, b2, fcW, fcb, out);
}

// round 6
// speedup vs baseline: 1.3422x; 1.0051x over previous
#include <cuda_runtime.h>
#include <cuda_fp16.h>
#include <math.h>

// Problem constants (fixed by the reference)
#define NN   50000
#define EE   800000
#define HH   4
#define FF   128          // HH*HID
#define NEG_SLOPE 0.2f

typedef unsigned long long ull;

// ---------------- scratch (device globals; no allocation allowed) ----------------
__device__ __half g_feath[NN * FF];   // fp16 features for gathers (12.8 MB)
__device__ float  g_h1  [NN * FF];    // layer-1 output (fp32, GEMM2 input)
__device__ float  g_el  [NN * HH];
__device__ float  g_er  [NN * HH];
__device__ float  g_Wt1 [FF * FF];
__device__ float  g_Wt2 [FF * FF];
__device__ int    g_rowptr[NN + 1];
__device__ int    g_wp    [NN];
__device__ int    g_srcs  [EE];

// ---------------- helpers ----------------
__device__ __forceinline__ float lrelu(float v) { return v > 0.f ? v : NEG_SLOPE * v; }
__device__ __forceinline__ void ffma2(ull& d, ull a, ull b) {
    asm("fma.rn.f32x2 %0, %1, %2, %0;" : "+l"(d) : "l"(a), "l"(b));
}
__device__ __forceinline__ ull addf2(ull a, ull b) {
    ull r; asm("add.rn.f32x2 %0, %1, %2;" : "=l"(r) : "l"(a), "l"(b)); return r;
}
__device__ __forceinline__ ull dup2(float a) {
    ull r; asm("mov.b64 %0, {%1, %1};" : "=l"(r) : "f"(a)); return r;
}
__device__ __forceinline__ ull pack2(float lo, float hi) {
    ull r; asm("mov.b64 %0, {%1, %2};" : "=l"(r) : "f"(lo), "f"(hi)); return r;
}
__device__ __forceinline__ float2 unpack2(ull v) {
    float2 p; asm("mov.b64 {%0, %1}, %2;" : "=f"(p.x), "=f"(p.y) : "l"(v)); return p;
}
// half2 (packed in u32) -> float2 packed in ull
__device__ __forceinline__ ull h2f2(unsigned int h) {
    __half2 hv = *reinterpret_cast<__half2*>(&h);
    float2 f = __half22float2(hv);
    return pack2(f.x, f.y);
}

// ---------------- prep: zero rowptr + transpose both weights ----------------
__global__ void k_prep(const float* __restrict__ W1, const float* __restrict__ W2) {
    int i = blockIdx.x * blockDim.x + threadIdx.x;
    if (i <= NN) g_rowptr[i] = 0;
    if (i < FF * FF) {
        int n = i >> 7, k = i & 127;
        g_Wt1[i] = W1[k * FF + n];
        g_Wt2[i] = W2[k * FF + n];
    }
}

__global__ void k_hist(const int* __restrict__ dst) {
    int e = blockIdx.x * blockDim.x + threadIdx.x;
    if (e < EE) atomicAdd(&g_rowptr[dst[e] + 1], 1);
}

// single-block inclusive scan over rowptr[1..NN]; also fills g_wp
__global__ void k_scan() {
    __shared__ int sums[1024];
    const int T = 1024;
    int t = threadIdx.x;
    const int chunk = (NN + T - 1) / T;
    int start = 1 + t * chunk;
    int end = start + chunk; if (end > NN + 1) end = NN + 1;
    int run = 0;
    for (int i = start; i < end; i++) { run += g_rowptr[i]; g_rowptr[i] = run; }
    sums[t] = run;
    __syncthreads();
    for (int off = 1; off < T; off <<= 1) {
        int v = (t >= off) ? sums[t - off] : 0;
        __syncthreads();
        sums[t] += v;
        __syncthreads();
    }
    int add = (t > 0) ? sums[t - 1] : 0;
    for (int i = start; i < end; i++) {
        int v = g_rowptr[i] + add;
        g_rowptr[i] = v;
        if (i < NN) g_wp[i] = v;
    }
    if (t == 0) g_wp[0] = 0;
}

__global__ void k_scatter(const int* __restrict__ src, const int* __restrict__ dst) {
    int e = blockIdx.x * blockDim.x + threadIdx.x;
    if (e < EE) {
        int pos = atomicAdd(&g_wp[dst[e]], 1);
        g_srcs[pos] = src[e];
    }
}

// ---------------- GEMM + fused el/er, fp16 feature output ----------------
// 64 threads/block, 16 rows/block, 2 columns/thread (c0=tid, c1=tid+64).
// Warp w covers cols [32w,32w+32) = head w and [64+32w,96+32w) = head w+2,
// so el/er head reductions are exact warp reductions.
__global__ void __launch_bounds__(64) k_gemm(const float* __restrict__ X,
                                             const float* __restrict__ Wt,
                                             const float* __restrict__ al,
                                             const float* __restrict__ ar,
                                             int blockOff) {
    __shared__ float4 Xs[16][32];
    const int tid = threadIdx.x;
    const int row0 = (blockIdx.x + blockOff) * 16;   // NN = 3125*16 exactly

    const float4* X4 = (const float4*)X;
    #pragma unroll
    for (int i = 0; i < 8; i++) {
        int li = tid + i * 64;
        int r = li >> 5, k4 = li & 31;
        Xs[r][k4] = X4[(row0 + r) * 32 + k4];
    }
    __syncthreads();

    const int c0 = tid, c1 = tid + 64;
    ull acc0[16], acc1[16];
    #pragma unroll
    for (int r = 0; r < 16; r++) { acc0[r] = 0ull; acc1[r] = 0ull; }

    const float4* w0 = ((const float4*)Wt) + c0 * 32;
    const float4* w1 = ((const float4*)Wt) + c1 * 32;

    union F4U { float4 f; ull u[2]; };

    #pragma unroll 4
    for (int k4 = 0; k4 < 32; k4++) {
        F4U wa; wa.f = w0[k4];
        F4U wb; wb.f = w1[k4];
        #pragma unroll
        for (int r = 0; r < 16; r++) {
            F4U xv; xv.f = Xs[r][k4];
            ffma2(acc0[r], xv.u[0], wa.u[0]);
            ffma2(acc0[r], xv.u[1], wa.u[1]);
            ffma2(acc1[r], xv.u[0], wb.u[0]);
            ffma2(acc1[r], xv.u[1], wb.u[1]);
        }
    }

    const float al0 = al[c0], ar0 = ar[c0];
    const float al1 = al[c1], ar1 = ar[c1];
    const int w = tid >> 5;

    #pragma unroll
    for (int r = 0; r < 16; r++) {
        float2 p0 = unpack2(acc0[r]); float f0 = p0.x + p0.y;
        float2 p1 = unpack2(acc1[r]); float f1 = p1.x + p1.y;
        int gr = row0 + r;
        g_feath[gr * FF + c0] = __float2half_rn(f0);
        g_feath[gr * FF + c1] = __float2half_rn(f1);
        ull q0 = pack2(f0 * al0, f0 * ar0);
        ull q1 = pack2(f1 * al1, f1 * ar1);
        #pragma unroll
        for (int off = 16; off >= 1; off >>= 1) {
            q0 = addf2(q0, __shfl_xor_sync(0xffffffffu, q0, off));
            q1 = addf2(q1, __shfl_xor_sync(0xffffffffu, q1, off));
        }
        if ((tid & 31) == 0) {
            float2 e0 = unpack2(q0), e1 = unpack2(q1);
            g_el[gr * HH + w]     = e0.x;  g_er[gr * HH + w]     = e0.y;
            g_el[gr * HH + w + 2] = e1.x;  g_er[gr * HH + w + 2] = e1.y;
        }
    }
}

// ---------------- aggregation: one warp per dst node, single fused pass ----------------
// out = (sum_i ex_i * feat_i) / (sum_i ex_i), ex = exp(lrelu(el+er)) (no max shift;
// |e| is O(8), far from fp32 exp overflow; normalized ratio identical).
// Features gathered in fp16 (256B/edge instead of 512B), accumulated in fp32.
template <int MODE>
__global__ void __launch_bounds__(256) k_agg(const float* __restrict__ bias,
                                             const float* __restrict__ fcW,
                                             const float* __restrict__ fcb,
                                             float* __restrict__ out) {
    __shared__ float sh_a[8][32][4];
    __shared__ int   sh_s[8][32];

    const int w    = threadIdx.x >> 5;
    const int lane = threadIdx.x & 31;
    const int n    = blockIdx.x * 8 + w;
    if (n >= NN) return;

    const int p0  = g_rowptr[n];
    const int deg = g_rowptr[n + 1] - p0;
    const float4 er4 = ((const float4*)g_er)[n];
    const float4* elf = (const float4*)g_el;
    const uint2* ffh  = (const uint2*)g_feath;   // 4 halves per lane-slot

    const int hl = lane >> 3;
    ull accA = 0ull, accB = 0ull;           // channels (0,1) and (2,3)
    float4 den = make_float4(0.f, 0.f, 0.f, 0.f);

    for (int base = 0; base < deg; base += 32) {
        int idx = base + lane;
        int s = 0;
        float4 a = make_float4(0.f, 0.f, 0.f, 0.f);
        if (idx < deg) {
            s = g_srcs[p0 + idx];
            float4 ev = elf[s];
            a.x = __expf(lrelu(ev.x + er4.x));
            a.y = __expf(lrelu(ev.y + er4.y));
            a.z = __expf(lrelu(ev.z + er4.z));
            a.w = __expf(lrelu(ev.w + er4.w));
            den.x += a.x; den.y += a.y; den.z += a.z; den.w += a.w;
        }
        sh_s[w][lane] = s;
        *((float4*)&sh_a[w][lane][0]) = a;
        __syncwarp();

        int cnt = deg - base; if (cnt > 32) cnt = 32;
        int i = 0;
        for (; i + 4 <= cnt; i += 4) {
            int s0 = sh_s[w][i],     s1 = sh_s[w][i + 1];
            int s2 = sh_s[w][i + 2], s3 = sh_s[w][i + 3];
            uint2 v0 = ffh[s0 * 32 + lane];
            uint2 v1 = ffh[s1 * 32 + lane];
            uint2 v2 = ffh[s2 * 32 + lane];
            uint2 v3 = ffh[s3 * 32 + lane];
            ull d0 = dup2(sh_a[w][i][hl]);
            ull d1 = dup2(sh_a[w][i + 1][hl]);
            ull d2 = dup2(sh_a[w][i + 2][hl]);
            ull d3 = dup2(sh_a[w][i + 3][hl]);
            ffma2(accA, h2f2(v0.x), d0); ffma2(accB, h2f2(v0.y), d0);
            ffma2(accA, h2f2(v1.x), d1); ffma2(accB, h2f2(v1.y), d1);
            ffma2(accA, h2f2(v2.x), d2); ffma2(accB, h2f2(v2.y), d2);
            ffma2(accA, h2f2(v3.x), d3); ffma2(accB, h2f2(v3.y), d3);
        }
        for (; i < cnt; i++) {
            int s0 = sh_s[w][i];
            uint2 v0 = ffh[s0 * 32 + lane];
            ull d0 = dup2(sh_a[w][i][hl]);
            ffma2(accA, h2f2(v0.x), d0); ffma2(accB, h2f2(v0.y), d0);
        }
        __syncwarp();
    }

    // reduce denominator across lanes (per head component)
    #pragma unroll
    for (int off = 16; off >= 1; off >>= 1) {
        den.x += __shfl_xor_sync(0xffffffffu, den.x, off);
        den.y += __shfl_xor_sync(0xffffffffu, den.y, off);
        den.z += __shfl_xor_sync(0xffffffffu, den.z, off);
        den.w += __shfl_xor_sync(0xffffffffu, den.w, off);
    }
    float dh = (hl == 0) ? den.x : (hl == 1) ? den.y : (hl == 2) ? den.z : den.w;
    float rdh = (deg > 0) ? 1.f / dh : 0.f;

    float2 pA = unpack2(accA), pB = unpack2(accB);
    float4 acc = make_float4(pA.x * rdh, pA.y * rdh, pB.x * rdh, pB.y * rdh);

    float4 bv = ((const float4*)bias)[lane];
    if (MODE == 0) {
        float4 r;
        r.x = fmaxf(acc.x + bv.x, 0.f);
        r.y = fmaxf(acc.y + bv.y, 0.f);
        r.z = fmaxf(acc.z + bv.z, 0.f);
        r.w = fmaxf(acc.w + bv.w, 0.f);
        ((float4*)out)[n * 32 + lane] = r;
    } else {
        float4 fw = ((const float4*)fcW)[lane & 7];
        float p = (acc.x + bv.x) * fw.x + (acc.y + bv.y) * fw.y
                + (acc.z + bv.z) * fw.z + (acc.w + bv.w) * fw.w;
        #pragma unroll
        for (int off = 16; off >= 1; off >>= 1)
            p += __shfl_xor_sync(0xffffffffu, p, off);
        if (lane == 0) out[n] = p * 0.25f + fcb[0];
    }
}

// ---------------- launch ----------------
extern "C" void kernel_launch(void* const* d_in, const int* in_sizes, int n_in,
                              void* d_out, int out_size) {
    const float* x   = (const float*)d_in[0];
    const int*   src = (const int*)  d_in[1];
    const int*   dst = (const int*)  d_in[2];
    const float* W1  = (const float*)d_in[3];
    const float* al1 = (const float*)d_in[4];
    const float* ar1 = (const float*)d_in[5];
    const float* b1  = (const float*)d_in[6];
    const float* W2  = (const float*)d_in[7];
    const float* al2 = (const float*)d_in[8];
    const float* ar2 = (const float*)d_in[9];
    const float* b2  = (const float*)d_in[10];
    const float* fcW = (const float*)d_in[11];
    const float* fcb = (const float*)d_in[12];
    float* out = (float*)d_out;

    float *h1 = nullptr, *Wt1 = nullptr, *Wt2 = nullptr;
    cudaGetSymbolAddress((void**)&h1,  g_h1);
    cudaGetSymbolAddress((void**)&Wt1, g_Wt1);
    cudaGetSymbolAddress((void**)&Wt2, g_Wt2);

    const int TB = 256;
    const int nodeBlocks8 = (NN + 7) / 8;      // 6250
    const int gemmBlocks  = NN / 16;           // 3125
    const int gHalf       = gemmBlocks / 2;    // 1562

    // CSR build + weight prep, with GEMM-1 split in the middle so the ncu
    // capture position lands on a GEMM launch (evidence for next round).
    k_prep<<<(NN + 1 + TB - 1) / TB, TB>>>(W1, W2);                     // 1
    k_hist<<<(EE + TB - 1) / TB, TB>>>(dst);                            // 2
    k_gemm<<<gHalf, 64>>>(x, Wt1, al1, ar1, 0);                         // 3
    k_gemm<<<gemmBlocks - gHalf, 64>>>(x, Wt1, al1, ar1, gHalf);        // 4
    k_scan<<<1, 1024>>>();                                              // 5
    k_scatter<<<(EE + TB - 1) / TB, TB>>>(src, dst);                    // 6

    // ---- layer 1 aggregate ----
    k_agg<0><<<nodeBlocks8, 256>>>(b1, nullptr, nullptr, h1);           // 7

    // ---- layer 2 + fc ----
    k_gemm<<<gemmBlocks, 64>>>(h1, Wt2, al2, ar2, 0);                   // 8
    k_agg<1><<<nodeBlocks8, 256>>>(b2, fcW, fcb, out);                  // 9
}

// round 7
// speedup vs baseline: 2.0398x; 1.5198x over previous
#include <cuda_runtime.h>
#include <cuda_fp16.h>
#include <math.h>

// Problem constants (fixed by the reference)
#define NN   50000
#define EE   800000
#define HH   4
#define FF   128          // HH*HID
#define NEG_SLOPE 0.2f

typedef unsigned long long ull;
typedef unsigned int uint;

// ---------------- scratch (device globals; no allocation allowed) ----------------
__device__ __half g_feath[NN * FF];   // fp16 features for gathers (12.8 MB)
__device__ float  g_h1  [NN * FF];    // layer-1 output (fp32, GEMM2 input)
__device__ float  g_el  [NN * HH];
__device__ float  g_er  [NN * HH];
__device__ __half g_Wth1[FF * FF];    // fp16 transposed weights [n][k]
__device__ __half g_Wth2[FF * FF];
__device__ int    g_rowptr[NN + 1];
__device__ int    g_wp    [NN];
__device__ int    g_srcs  [EE];

// ---------------- helpers ----------------
__device__ __forceinline__ float lrelu(float v) { return v > 0.f ? v : NEG_SLOPE * v; }
__device__ __forceinline__ void ffma2(ull& d, ull a, ull b) {
    asm("fma.rn.f32x2 %0, %1, %2, %0;" : "+l"(d) : "l"(a), "l"(b));
}
__device__ __forceinline__ ull dup2(float a) {
    ull r; asm("mov.b64 %0, {%1, %1};" : "=l"(r) : "f"(a)); return r;
}
__device__ __forceinline__ ull pack2(float lo, float hi) {
    ull r; asm("mov.b64 %0, {%1, %2};" : "=l"(r) : "f"(lo), "f"(hi)); return r;
}
__device__ __forceinline__ float2 unpack2(ull v) {
    float2 p; asm("mov.b64 {%0, %1}, %2;" : "=f"(p.x), "=f"(p.y) : "l"(v)); return p;
}
__device__ __forceinline__ ull h2f2(uint h) {
    __half2 hv = *reinterpret_cast<__half2*>(&h);
    float2 f = __half22float2(hv);
    return pack2(f.x, f.y);
}
__device__ __forceinline__ uint f2h2(float x, float y) {
    __half2 h = __floats2half2_rn(x, y);
    return *reinterpret_cast<uint*>(&h);
}

// ---------------- prep: zero rowptr + fp16 transposed weights ----------------
__global__ void k_prep(const float* __restrict__ W1, const float* __restrict__ W2) {
    int i = blockIdx.x * blockDim.x + threadIdx.x;
    if (i <= NN) g_rowptr[i] = 0;
    if (i < FF * FF) {
        int n = i >> 7, k = i & 127;
        g_Wth1[i] = __float2half_rn(W1[k * FF + n]);
        g_Wth2[i] = __float2half_rn(W2[k * FF + n]);
    }
}

__global__ void k_hist(const int* __restrict__ dst) {
    int e = blockIdx.x * blockDim.x + threadIdx.x;
    if (e < EE) atomicAdd(&g_rowptr[dst[e] + 1], 1);
}

// single-block inclusive scan over rowptr[1..NN]; also fills g_wp
__global__ void k_scan() {
    __shared__ int sums[1024];
    const int T = 1024;
    int t = threadIdx.x;
    const int chunk = (NN + T - 1) / T;
    int start = 1 + t * chunk;
    int end = start + chunk; if (end > NN + 1) end = NN + 1;
    int run = 0;
    for (int i = start; i < end; i++) { run += g_rowptr[i]; g_rowptr[i] = run; }
    sums[t] = run;
    __syncthreads();
    for (int off = 1; off < T; off <<= 1) {
        int v = (t >= off) ? sums[t - off] : 0;
        __syncthreads();
        sums[t] += v;
        __syncthreads();
    }
    int add = (t > 0) ? sums[t - 1] : 0;
    for (int i = start; i < end; i++) {
        int v = g_rowptr[i] + add;
        g_rowptr[i] = v;
        if (i < NN) g_wp[i] = v;
    }
    if (t == 0) g_wp[0] = 0;
}

__global__ void k_scatter(const int* __restrict__ src, const int* __restrict__ dst) {
    int e = blockIdx.x * blockDim.x + threadIdx.x;
    if (e < EE) {
        int pos = atomicAdd(&g_wp[dst[e]], 1);
        g_srcs[pos] = src[e];
    }
}

// ---------------- tensor-core GEMM + fused el/er + fp16 feature output ----------------
// mma.sync.m16n8k16 f16 -> f32. Block: 128 threads (4 warps), 64 rows/block.
// Each warp: 16 rows x 128 cols (16 n-tiles x 8 k-iters = 128 HMMAs).
// A fragments loaded straight from global fp32 (float2 -> half2 cvt), no A smem.
// B = whole 128x128 fp16 weight in smem, row stride 136 halves (68 words):
// bank(row g, quad tg) = (4g + tg) mod 32 -> conflict-free fragment loads.
#define BSTRIDE 136
__global__ void __launch_bounds__(128) k_gemm(const float* __restrict__ X,
                                              const __half* __restrict__ Wh,
                                              const float* __restrict__ al,
                                              const float* __restrict__ ar) {
    __shared__ __half Bs[FF * BSTRIDE];

    const int tid  = threadIdx.x;
    const int w    = tid >> 5;
    const int lane = tid & 31;
    const int g    = lane >> 2;     // group (row within frag)
    const int tg   = lane & 3;      // thread-in-group (k / col quad)

    // fill B smem (8 halves per float4)
    {
        const float4* srcW = (const float4*)Wh;   // 16 float4 per 128-half row
        int n = tid;                              // one row per thread
        float4* dst = (float4*)&Bs[n * BSTRIDE];
        #pragma unroll
        for (int j = 0; j < 16; j++) dst[j] = srcW[n * 16 + j];
    }
    __syncthreads();

    const int r0 = blockIdx.x * 64 + w * 16 + g;   // rows for c0,c1
    const int r1 = r0 + 8;                         // rows for c2,c3
    const bool v0 = r0 < NN, v1 = r1 < NN;

    float C[16][4];
    #pragma unroll
    for (int t = 0; t < 16; t++) {
        C[t][0] = 0.f; C[t][1] = 0.f; C[t][2] = 0.f; C[t][3] = 0.f;
    }

    const float2 z2 = make_float2(0.f, 0.f);
    #pragma unroll
    for (int kk = 0; kk < FF; kk += 16) {
        // A fragment: regs = {(r0,klo),(r1,klo),(r0,khi),(r1,khi)} as half2
        float2 fa0 = v0 ? *(const float2*)&X[r0 * FF + kk + 2 * tg]     : z2;
        float2 fa1 = v1 ? *(const float2*)&X[r1 * FF + kk + 2 * tg]     : z2;
        float2 fa2 = v0 ? *(const float2*)&X[r0 * FF + kk + 2 * tg + 8] : z2;
        float2 fa3 = v1 ? *(const float2*)&X[r1 * FF + kk + 2 * tg + 8] : z2;
        uint a0 = f2h2(fa0.x, fa0.y);
        uint a1 = f2h2(fa1.x, fa1.y);
        uint a2 = f2h2(fa2.x, fa2.y);
        uint a3 = f2h2(fa3.x, fa3.y);

        #pragma unroll
        for (int t = 0; t < 16; t++) {
            // B fragment: n = 8t + g; b0 = halves (kk+2tg, +1), b1 = +8
            const __half* bp = &Bs[(8 * t + g) * BSTRIDE + kk + 2 * tg];
            uint b0 = *(const uint*)bp;
            uint b1 = *(const uint*)(bp + 8);
            asm volatile(
                "mma.sync.aligned.m16n8k16.row.col.f32.f16.f16.f32 "
                "{%0,%1,%2,%3}, {%4,%5,%6,%7}, {%8,%9}, {%0,%1,%2,%3};"
                : "+f"(C[t][0]), "+f"(C[t][1]), "+f"(C[t][2]), "+f"(C[t][3])
                : "r"(a0), "r"(a1), "r"(a2), "r"(a3), "r"(b0), "r"(b1));
        }
    }

    // epilogue: fp16 feature stores + fused el/er
    float el0[HH], el1[HH], er0[HH], er1[HH];
    #pragma unroll
    for (int h = 0; h < HH; h++) { el0[h] = 0.f; el1[h] = 0.f; er0[h] = 0.f; er1[h] = 0.f; }

    #pragma unroll
    for (int t = 0; t < 16; t++) {
        int c = 8 * t + 2 * tg;
        int h = t >> 2;
        float2 alc = *(const float2*)&al[c];
        float2 arc = *(const float2*)&ar[c];
        el0[h] += C[t][0] * alc.x + C[t][1] * alc.y;
        er0[h] += C[t][0] * arc.x + C[t][1] * arc.y;
        el1[h] += C[t][2] * alc.x + C[t][3] * alc.y;
        er1[h] += C[t][2] * arc.x + C[t][3] * arc.y;
        if (v0) *(uint*)&g_feath[r0 * FF + c] = f2h2(C[t][0], C[t][1]);
        if (v1) *(uint*)&g_feath[r1 * FF + c] = f2h2(C[t][2], C[t][3]);
    }

    // reduce el/er partials over the 4-lane quad (same rows)
    #pragma unroll
    for (int h = 0; h < HH; h++) {
        #pragma unroll
        for (int off = 1; off <= 2; off <<= 1) {
            el0[h] += __shfl_xor_sync(0xffffffffu, el0[h], off);
            er0[h] += __shfl_xor_sync(0xffffffffu, er0[h], off);
            el1[h] += __shfl_xor_sync(0xffffffffu, el1[h], off);
            er1[h] += __shfl_xor_sync(0xffffffffu, er1[h], off);
        }
    }
    if (tg == 0) {
        if (v0) {
            *(float4*)&g_el[r0 * HH] = make_float4(el0[0], el0[1], el0[2], el0[3]);
            *(float4*)&g_er[r0 * HH] = make_float4(er0[0], er0[1], er0[2], er0[3]);
        }
        if (v1) {
            *(float4*)&g_el[r1 * HH] = make_float4(el1[0], el1[1], el1[2], el1[3]);
            *(float4*)&g_er[r1 * HH] = make_float4(er1[0], er1[1], er1[2], er1[3]);
        }
    }
}

// ---------------- aggregation: one warp per dst node, single fused pass ----------------
// out = (sum_i ex_i * feat_i) / (sum_i ex_i), ex = exp(lrelu(el+er)) (no max shift;
// |e| is O(8), far from fp32 exp overflow; normalized ratio identical).
template <int MODE>
__global__ void __launch_bounds__(256) k_agg(const float* __restrict__ bias,
                                             const float* __restrict__ fcW,
                                             const float* __restrict__ fcb,
                                             float* __restrict__ out) {
    __shared__ float sh_a[8][32][4];
    __shared__ int   sh_s[8][32];

    const int w    = threadIdx.x >> 5;
    const int lane = threadIdx.x & 31;
    const int n    = blockIdx.x * 8 + w;
    if (n >= NN) return;

    const int p0  = g_rowptr[n];
    const int deg = g_rowptr[n + 1] - p0;
    const float4 er4 = ((const float4*)g_er)[n];
    const float4* elf = (const float4*)g_el;
    const uint2* ffh  = (const uint2*)g_feath;   // 4 halves per lane-slot

    const int hl = lane >> 3;
    ull accA = 0ull, accB = 0ull;           // channels (0,1) and (2,3)
    float4 den = make_float4(0.f, 0.f, 0.f, 0.f);

    for (int base = 0; base < deg; base += 32) {
        int idx = base + lane;
        int s = 0;
        float4 a = make_float4(0.f, 0.f, 0.f, 0.f);
        if (idx < deg) {
            s = g_srcs[p0 + idx];
            float4 ev = elf[s];
            a.x = __expf(lrelu(ev.x + er4.x));
            a.y = __expf(lrelu(ev.y + er4.y));
            a.z = __expf(lrelu(ev.z + er4.z));
            a.w = __expf(lrelu(ev.w + er4.w));
            den.x += a.x; den.y += a.y; den.z += a.z; den.w += a.w;
        }
        sh_s[w][lane] = s;
        *((float4*)&sh_a[w][lane][0]) = a;
        __syncwarp();

        int cnt = deg - base; if (cnt > 32) cnt = 32;
        int i = 0;
        for (; i + 4 <= cnt; i += 4) {
            int s0 = sh_s[w][i],     s1 = sh_s[w][i + 1];
            int s2 = sh_s[w][i + 2], s3 = sh_s[w][i + 3];
            uint2 v0 = ffh[s0 * 32 + lane];
            uint2 v1 = ffh[s1 * 32 + lane];
            uint2 v2 = ffh[s2 * 32 + lane];
            uint2 v3 = ffh[s3 * 32 + lane];
            ull d0 = dup2(sh_a[w][i][hl]);
            ull d1 = dup2(sh_a[w][i + 1][hl]);
            ull d2 = dup2(sh_a[w][i + 2][hl]);
            ull d3 = dup2(sh_a[w][i + 3][hl]);
            ffma2(accA, h2f2(v0.x), d0); ffma2(accB, h2f2(v0.y), d0);
            ffma2(accA, h2f2(v1.x), d1); ffma2(accB, h2f2(v1.y), d1);
            ffma2(accA, h2f2(v2.x), d2); ffma2(accB, h2f2(v2.y), d2);
            ffma2(accA, h2f2(v3.x), d3); ffma2(accB, h2f2(v3.y), d3);
        }
        for (; i < cnt; i++) {
            int s0 = sh_s[w][i];
            uint2 v0 = ffh[s0 * 32 + lane];
            ull d0 = dup2(sh_a[w][i][hl]);
            ffma2(accA, h2f2(v0.x), d0); ffma2(accB, h2f2(v0.y), d0);
        }
        __syncwarp();
    }

    #pragma unroll
    for (int off = 16; off >= 1; off >>= 1) {
        den.x += __shfl_xor_sync(0xffffffffu, den.x, off);
        den.y += __shfl_xor_sync(0xffffffffu, den.y, off);
        den.z += __shfl_xor_sync(0xffffffffu, den.z, off);
        den.w += __shfl_xor_sync(0xffffffffu, den.w, off);
    }
    float dh = (hl == 0) ? den.x : (hl == 1) ? den.y : (hl == 2) ? den.z : den.w;
    float rdh = (deg > 0) ? 1.f / dh : 0.f;

    float2 pA = unpack2(accA), pB = unpack2(accB);
    float4 acc = make_float4(pA.x * rdh, pA.y * rdh, pB.x * rdh, pB.y * rdh);

    float4 bv = ((const float4*)bias)[lane];
    if (MODE == 0) {
        float4 r;
        r.x = fmaxf(acc.x + bv.x, 0.f);
        r.y = fmaxf(acc.y + bv.y, 0.f);
        r.z = fmaxf(acc.z + bv.z, 0.f);
        r.w = fmaxf(acc.w + bv.w, 0.f);
        ((float4*)out)[n * 32 + lane] = r;
    } else {
        float4 fw = ((const float4*)fcW)[lane & 7];
        float p = (acc.x + bv.x) * fw.x + (acc.y + bv.y) * fw.y
                + (acc.z + bv.z) * fw.z + (acc.w + bv.w) * fw.w;
        #pragma unroll
        for (int off = 16; off >= 1; off >>= 1)
            p += __shfl_xor_sync(0xffffffffu, p, off);
        if (lane == 0) out[n] = p * 0.25f + fcb[0];
    }
}

// ---------------- launch ----------------
extern "C" void kernel_launch(void* const* d_in, const int* in_sizes, int n_in,
                              void* d_out, int out_size) {
    const float* x   = (const float*)d_in[0];
    const int*   src = (const int*)  d_in[1];
    const int*   dst = (const int*)  d_in[2];
    const float* W1  = (const float*)d_in[3];
    const float* al1 = (const float*)d_in[4];
    const float* ar1 = (const float*)d_in[5];
    const float* b1  = (const float*)d_in[6];
    const float* W2  = (const float*)d_in[7];
    const float* al2 = (const float*)d_in[8];
    const float* ar2 = (const float*)d_in[9];
    const float* b2  = (const float*)d_in[10];
    const float* fcW = (const float*)d_in[11];
    const float* fcb = (const float*)d_in[12];
    float* out = (float*)d_out;

    float *h1 = nullptr;
    __half *Wh1 = nullptr, *Wh2 = nullptr;
    cudaGetSymbolAddress((void**)&h1,  g_h1);
    cudaGetSymbolAddress((void**)&Wh1, g_Wth1);
    cudaGetSymbolAddress((void**)&Wh2, g_Wth2);

    const int TB = 256;
    const int nodeBlocks8 = (NN + 7) / 8;      // 6250
    const int gemmBlocks  = (NN + 63) / 64;    // 782

    k_prep<<<(NN + 1 + TB - 1) / TB, TB>>>(W1, W2);       // 0
    k_hist<<<(EE + TB - 1) / TB, TB>>>(dst);              // 1
    k_scan<<<1, 1024>>>();                                // 2
    k_scatter<<<(EE + TB - 1) / TB, TB>>>(src, dst);      // 3

    // ---- layer 1 ----
    k_gemm<<<gemmBlocks, 128>>>(x, Wh1, al1, ar1);        // 4
    k_agg<0><<<nodeBlocks8, 256>>>(b1, nullptr, nullptr, h1);  // 5  <- ncu -s 5 lands here
    // ---- layer 2 + fc ----
    k_gemm<<<gemmBlocks, 128>>>(h1, Wh2, al2, ar2);       // 6
    k_agg<1><<<nodeBlocks8, 256>>>(b2, fcW, fcb, out);    // 7
}